// round 6
// baseline (speedup 1.0000x reference)
#include <cuda_runtime.h>
#include <cstdint>

#define B_ROWS 4096
#define M_COLS 16384
#define D_DIM  512
#define N_BMU  16

// Constants exactly as JAX folds them to fp32:
#define C1 ((float)(2.0 * 1e-6))               // 2.0*EPS
#define C2 ((float)(512.0 * (1e-6 * 1e-6)))    // d*EPS^2

// Scratch (no cudaMalloc allowed)
__device__ float g_dist[(size_t)B_ROWS * M_COLS];
__device__ float g_w2[M_COLS];
__device__ float g_sw[M_COLS];
__device__ float g_x2[B_ROWS];
__device__ float g_sx[B_ROWS];

// ---------------------------------------------------------------------------
// Column stats, maximally accurate ("center" of all accurate reductions):
// fp64 accumulation of fp32-rounded squares, single rounding to fp32 at end.
// One thread per column m; loads coalesced across m.
// ---------------------------------------------------------------------------
__global__ __launch_bounds__(256)
void wstats_kernel(const float* __restrict__ w) {
    int m = blockIdx.x * blockDim.x + threadIdx.x;
    if (m >= M_COLS) return;
    double w2 = 0.0, sw = 0.0;
    for (int d = 0; d < D_DIM; ++d) {
        float v = w[(size_t)d * M_COLS + m];
        w2 += (double)__fmul_rn(v, v);   // fp32-rounded square, near-exact sum
        sw += (double)v;
    }
    g_w2[m] = (float)w2;
    g_sw[m] = (float)sw;
}

// ---------------------------------------------------------------------------
// Row stats: fp64 accumulation per row (one warp per row), near-exact.
// ---------------------------------------------------------------------------
__global__ __launch_bounds__(256)
void xstats_kernel(const float* __restrict__ x) {
    const int row = blockIdx.x * 8 + (threadIdx.x >> 5);
    const int lane = threadIdx.x & 31;
    if (row >= B_ROWS) return;
    const float* xr = x + (size_t)row * D_DIM;

    double p2 = 0.0, p1 = 0.0;
    for (int i = lane; i < D_DIM; i += 32) {
        float v = xr[i];
        p2 += (double)__fmul_rn(v, v);
        p1 += (double)v;
    }
    #pragma unroll
    for (int off = 16; off; off >>= 1) {
        p2 += __shfl_xor_sync(0xffffffffu, p2, off);
        p1 += __shfl_xor_sync(0xffffffffu, p1, off);
    }
    if (lane == 0) { g_x2[row] = (float)p2; g_sx[row] = (float)p1; }
}

// ---------------------------------------------------------------------------
// SGEMM: SINGLE serial ascending-k fp32 FMA chain per output element
// (bitwise matches the cuBLAS per-thread mainloop). Fused distance epilogue
// replicating the XLA elementwise expression left-associatively, no FMA:
//   sq = ((((x2 - 2*xw) + w2) + C1*(sx - sw)) + C2); dist = sqrt(max(sq,0))
// 128x128 tile, BK=16, 256 threads, 8x8 per-thread accumulators.
// ---------------------------------------------------------------------------
#define BM 128
#define BN 128
#define BK 16

__global__ __launch_bounds__(256, 2)
void gemm_dist_kernel(const float* __restrict__ A, const float* __restrict__ W) {
    __shared__ float As[BK][BM];
    __shared__ float Bs[BK][BN];

    const int tid = threadIdx.x;
    const int tx = tid & 15;        // 16 column-groups of 8
    const int ty = tid >> 4;        // 16 row-groups of 8
    const int rowBase = blockIdx.y * BM;
    const int colBase = blockIdx.x * BN;

    const int arow = tid >> 2;            // 0..63 (two passes -> 128 rows)
    const int akq  = (tid & 3) * 4;       // k offset 0,4,8,12
    const int bk = tid >> 5;              // 0..7 (two passes -> 16 k)
    const int bc = (tid & 31) * 4;

    float acc[8][8];
    #pragma unroll
    for (int i = 0; i < 8; ++i)
        #pragma unroll
        for (int j = 0; j < 8; ++j) acc[i][j] = 0.f;

    for (int k0 = 0; k0 < D_DIM; k0 += BK) {
        #pragma unroll
        for (int p = 0; p < 2; ++p) {
            int r = arow + p * 64;
            float4 v = *(const float4*)(A + (size_t)(rowBase + r) * D_DIM + k0 + akq);
            As[akq + 0][r] = v.x; As[akq + 1][r] = v.y;
            As[akq + 2][r] = v.z; As[akq + 3][r] = v.w;
        }
        #pragma unroll
        for (int p = 0; p < 2; ++p) {
            int kk = bk + p * 8;
            float4 v = *(const float4*)(W + (size_t)(k0 + kk) * M_COLS + colBase + bc);
            *(float4*)&Bs[kk][bc] = v;
        }
        __syncthreads();

        #pragma unroll
        for (int kk = 0; kk < BK; ++kk) {   // ascending k: single FMA chain
            float a[8], b[8];
            *(float4*)(a)     = *(const float4*)&As[kk][ty * 8];
            *(float4*)(a + 4) = *(const float4*)&As[kk][ty * 8 + 4];
            *(float4*)(b)     = *(const float4*)&Bs[kk][tx * 8];
            *(float4*)(b + 4) = *(const float4*)&Bs[kk][tx * 8 + 4];
            #pragma unroll
            for (int i = 0; i < 8; ++i)
                #pragma unroll
                for (int j = 0; j < 8; ++j)
                    acc[i][j] = fmaf(a[i], b[j], acc[i][j]);
        }
        __syncthreads();
    }

    float x2v[8], sxv[8], w2v[8], swv[8];
    #pragma unroll
    for (int i = 0; i < 8; ++i) {
        x2v[i] = g_x2[rowBase + ty * 8 + i];
        sxv[i] = g_sx[rowBase + ty * 8 + i];
    }
    #pragma unroll
    for (int j = 0; j < 8; ++j) {
        w2v[j] = g_w2[colBase + tx * 8 + j];
        swv[j] = g_sw[colBase + tx * 8 + j];
    }

    #pragma unroll
    for (int i = 0; i < 8; ++i) {
        float d[8];
        #pragma unroll
        for (int j = 0; j < 8; ++j) {
            float t = __fsub_rn(x2v[i], __fmul_rn(2.0f, acc[i][j])); // x2 - 2*xw
            t = __fadd_rn(t, w2v[j]);                                 // + w2
            float ds = __fsub_rn(sxv[i], swv[j]);                     // (sx - sw)
            t = __fadd_rn(t, __fmul_rn(C1, ds));                      // + 2eps*(...)
            t = __fadd_rn(t, C2);                                     // + d*eps^2
            d[j] = sqrtf(fmaxf(t, 0.0f));
        }
        float* dst = g_dist + (size_t)(rowBase + ty * 8 + i) * M_COLS + colBase + tx * 8;
        *(float4*)(dst)     = *(float4*)(d);
        *(float4*)(dst + 4) = *(float4*)(d + 4);
    }
}

// ---------------------------------------------------------------------------
// Top-16 per query, one warp per row. Stable tie-break == jnp.argsort:
// key = (dist_bits << 32) | index, u64 ascending.
// ---------------------------------------------------------------------------
__global__ __launch_bounds__(256)
void topk_kernel(const float* __restrict__ loc, float* __restrict__ out) {
    const int q = blockIdx.x * 8 + (threadIdx.x >> 5);
    const int lane = threadIdx.x & 31;
    if (q >= B_ROWS) return;

    const float4* row = (const float4*)(g_dist + (size_t)q * M_COLS);

    unsigned long long t[N_BMU];
    #pragma unroll
    for (int s = 0; s < N_BMU; ++s) t[s] = ~0ULL;

    #pragma unroll 4
    for (int i = 0; i < M_COLS / (32 * 4); ++i) {
        int e = lane + i * 32;
        float4 v = row[e];
        int mbase = e * 4;
        float dv[4] = {v.x, v.y, v.z, v.w};
        #pragma unroll
        for (int j = 0; j < 4; ++j) {
            unsigned long long key =
                ((unsigned long long)__float_as_uint(dv[j]) << 32) |
                (unsigned)(mbase + j);
            if (key < t[N_BMU - 1]) {
                t[N_BMU - 1] = key;
                #pragma unroll
                for (int s = N_BMU - 1; s > 0; --s) {
                    if (t[s] < t[s - 1]) {
                        unsigned long long tmp = t[s - 1];
                        t[s - 1] = t[s];
                        t[s] = tmp;
                    }
                }
            }
        }
    }

    #pragma unroll 1
    for (int r = 0; r < N_BMU; ++r) {
        unsigned long long best = t[0];
        #pragma unroll
        for (int o = 16; o; o >>= 1) {
            unsigned long long other = __shfl_xor_sync(0xffffffffu, best, o);
            if (other < best) best = other;
        }
        if (lane == r) {
            int m = (int)(best & 0xffffffffULL);
            out[((size_t)r * B_ROWS + q) * 2 + 0] = loc[m * 2 + 0];
            out[((size_t)r * B_ROWS + q) * 2 + 1] = loc[m * 2 + 1];
        }
        if (t[0] == best) {  // keys unique -> exactly one lane pops
            #pragma unroll
            for (int s = 0; s < N_BMU - 1; ++s) t[s] = t[s + 1];
            t[N_BMU - 1] = ~0ULL;
        }
    }
}

__global__ void zero_tail_kernel(float* out, int start, int n) {
    int i = blockIdx.x * blockDim.x + threadIdx.x;
    if (i < n) out[start + i] = 0.0f;
}

extern "C" void kernel_launch(void* const* d_in, const int* in_sizes, int n_in,
                              void* d_out, int out_size) {
    const float* x   = (const float*)d_in[0];   // [4096, 512]
    const float* w   = (const float*)d_in[1];   // [512, 16384]
    const float* loc = (const float*)d_in[2];   // [16384, 2]
    float* out = (float*)d_out;

    wstats_kernel<<<M_COLS / 256, 256>>>(w);
    xstats_kernel<<<B_ROWS / 8, 256>>>(x);
    gemm_dist_kernel<<<dim3(M_COLS / BN, B_ROWS / BM), 256>>>(x, w);
    topk_kernel<<<B_ROWS / 8, 256>>>(loc, out);

    const int main_elems = N_BMU * B_ROWS * 2;  // 131072
    if (out_size > main_elems) {
        int tail = out_size - main_elems;
        zero_tail_kernel<<<(tail + 255) / 256, 256>>>(out, main_elems, tail);
    }
}